// round 12
// baseline (speedup 1.0000x reference)
#include <cuda_runtime.h>
#include <math.h>

// Fixed problem shapes
#define BB 8
#define SS 4096
#define HH 1152
#define LL 256
#define HV 288          // threads = float4 lanes per row
#define KK 4
#define BPB 4           // buckets per block
#define NW 9            // warps per block
#define CHUNK ((SS + NW - 1) / NW)   // 456

#define STASH_BYTES (SS * 8)         // int2 positions
#define PADW (SS / 4)                // pad bytes as words
#define DYN_SMEM (STASH_BYTES + PADW * 4 + SS * 4)  // 32768 + 4096 + 16384 = 53248

// ---------------------------------------------------------------------------
// Single fused kernel: each block builds token lists for its 4 buckets from
// ppi directly (L2-resident), then does the proven gather-accumulate.
// ---------------------------------------------------------------------------
__global__ __launch_bounds__(HV) void fused_pool(
    const float4* __restrict__ hs,
    const int2* __restrict__ ppi,
    const unsigned* __restrict__ padw,
    float4* __restrict__ out,
    float* __restrict__ mask,
    float scale)
{
    extern __shared__ unsigned char dsm[];
    int2* stash = (int2*)dsm;                                  // [SS]
    unsigned* spad = (unsigned*)(dsm + STASH_BYTES);           // [PADW]
    int* s_list = (int*)(dsm + STASH_BYTES + PADW * 4);        // [SS]

    __shared__ int s_wcnp[NW][BPB];
    __shared__ int s_wcall[NW][BPB];
    __shared__ int s_woff[NW][BPB];
    __shared__ int s_bstart[BPB];
    __shared__ int s_bcnt[BPB];
    __shared__ int s_ball[BPB];
    __shared__ int s_max[NW];
    __shared__ int s_factor;

    const int b = blockIdx.y;
    const int l0 = blockIdx.x * BPB;
    const int t = threadIdx.x;
    const int w = t >> 5;
    const int lane = t & 31;
    const unsigned lt = (1u << lane) - 1u;

    const int2* pb = ppi + (long long)b * SS;
    const unsigned* pw = padw + (long long)b * (SS / 4);

    // ---- Pass 1: stash positions + pad, reduce max_x ----
    int mx = 0;
    for (int s = t; s < SS; s += HV) {
        const int2 v = pb[s];
        stash[s] = v;
        mx = max(mx, v.x);
    }
    for (int i = t; i < PADW; i += HV) spad[i] = pw[i];
    #pragma unroll
    for (int off = 16; off > 0; off >>= 1)
        mx = max(mx, __shfl_xor_sync(0xFFFFFFFFu, mx, off));
    if (lane == 0) s_max[w] = mx;
    __syncthreads();
    if (t == 0) {
        int m = s_max[0];
        #pragma unroll
        for (int i = 1; i < NW; i++) m = max(m, s_max[i]);
        if (m < 0) m = 0;
        s_factor = (m + 1) / KK;
    }
    __syncthreads();
    const int factor = s_factor;

    const int begin = w * CHUNK;
    const int end = min(begin + CHUNK, SS);

    // ---- Pass 2: count matches per (warp, bucket) ----
    int cnp[BPB] = {0, 0, 0, 0};
    int call[BPB] = {0, 0, 0, 0};
    for (int sb = begin; sb < end; sb += 32) {
        const int s = sb + lane;
        int rel = -1;
        bool padded = false;
        if (s < end) {
            const int2 v = stash[s];
            padded = ((spad[s >> 2] >> ((s & 3) * 8)) & 0xFFu) != 0u;
            const int x = max(v.x, 0);
            const int y = max(v.y, 0);
            const long long kv = (long long)(x / KK)
                               + (long long)factor * (long long)(y / KK);
            if (kv >= l0 && kv < l0 + BPB) rel = (int)(kv - l0);
        }
        #pragma unroll
        for (int k = 0; k < BPB; k++) {
            const unsigned ba = __ballot_sync(0xFFFFFFFFu, rel == k);
            const unsigned bn = __ballot_sync(0xFFFFFFFFu, (rel == k) && !padded);
            call[k] += __popc(ba);
            cnp[k] += __popc(bn);
        }
    }
    if (lane == 0) {
        #pragma unroll
        for (int k = 0; k < BPB; k++) { s_wcnp[w][k] = cnp[k]; s_wcall[w][k] = call[k]; }
    }
    __syncthreads();

    if (t == 0) {
        int bstart = 0;
        #pragma unroll
        for (int k = 0; k < BPB; k++) {
            s_bstart[k] = bstart;
            int run = 0, all = 0;
            for (int ww = 0; ww < NW; ww++) {
                s_woff[ww][k] = bstart + run;
                run += s_wcnp[ww][k];
                all += s_wcall[ww][k];
            }
            s_bcnt[k] = run;
            s_ball[k] = all;
            bstart += run;
        }
    }
    __syncthreads();

    // ---- Pass 3: ballot-rank scatter (lists s-sorted, deterministic) ----
    int off[BPB];
    #pragma unroll
    for (int k = 0; k < BPB; k++) off[k] = s_woff[w][k];
    for (int sb = begin; sb < end; sb += 32) {
        const int s = sb + lane;
        int rel = -1;
        bool padded = false;
        if (s < end) {
            const int2 v = stash[s];
            padded = ((spad[s >> 2] >> ((s & 3) * 8)) & 0xFFu) != 0u;
            const int x = max(v.x, 0);
            const int y = max(v.y, 0);
            const long long kv = (long long)(x / KK)
                               + (long long)factor * (long long)(y / KK);
            if (kv >= l0 && kv < l0 + BPB) rel = (int)(kv - l0);
        }
        #pragma unroll
        for (int k = 0; k < BPB; k++) {
            const bool m = (rel == k) && !padded;
            const unsigned bn = __ballot_sync(0xFFFFFFFFu, m);
            if (m) s_list[off[k] + __popc(bn & lt)] = s;
            off[k] += __popc(bn);
        }
    }
    if (t < BPB && mask != nullptr)
        mask[(long long)b * LL + l0 + t] = (s_ball[t] > 0) ? 1.0f : 0.0f;
    __syncthreads();

    // ---- Accumulate: back-to-back buckets, 4-way unroll, streaming loads ----
    const float4* base4 = hs + (long long)b * SS * HV + t;
    #pragma unroll
    for (int k = 0; k < BPB; k++) {
        const int lo = s_bstart[k];
        const int n = s_bcnt[k];
        float4 a0 = make_float4(0.f, 0.f, 0.f, 0.f);
        float4 a1 = a0, a2 = a0, a3 = a0;
        int i = 0;
        for (; i + 4 <= n; i += 4) {
            const int q0 = s_list[lo + i],     q1 = s_list[lo + i + 1];
            const int q2 = s_list[lo + i + 2], q3 = s_list[lo + i + 3];
            const float4 x0 = __ldcs(base4 + (long long)q0 * HV);
            const float4 x1 = __ldcs(base4 + (long long)q1 * HV);
            const float4 x2 = __ldcs(base4 + (long long)q2 * HV);
            const float4 x3 = __ldcs(base4 + (long long)q3 * HV);
            a0.x += x0.x; a0.y += x0.y; a0.z += x0.z; a0.w += x0.w;
            a1.x += x1.x; a1.y += x1.y; a1.z += x1.z; a1.w += x1.w;
            a2.x += x2.x; a2.y += x2.y; a2.z += x2.z; a2.w += x2.w;
            a3.x += x3.x; a3.y += x3.y; a3.z += x3.z; a3.w += x3.w;
        }
        for (; i < n; i++) {
            const float4 x = __ldcs(base4 + (long long)s_list[lo + i] * HV);
            a0.x += x.x; a0.y += x.y; a0.z += x.z; a0.w += x.w;
        }
        float4 r;
        r.x = ((a0.x + a1.x) + (a2.x + a3.x)) * scale;
        r.y = ((a0.y + a1.y) + (a2.y + a3.y)) * scale;
        r.z = ((a0.z + a1.z) + (a2.z + a3.z)) * scale;
        r.w = ((a0.w + a1.w) + (a2.w + a3.w)) * scale;
        out[((long long)(b * LL + l0 + k)) * HV + t] = r;
    }
}

// ---------------------------------------------------------------------------
// Launch: one kernel, one graph node.
// ---------------------------------------------------------------------------
extern "C" void kernel_launch(void* const* d_in, const int* in_sizes, int n_in,
                              void* d_out, int out_size) {
    const float*    hs   = (const float*)d_in[0];
    const int2*     ppi  = (const int2*)d_in[1];
    const unsigned* padw = (const unsigned*)d_in[2];

    const float scale = sqrtf((float)HH) / (float)(KK * KK);

    float* out  = (float*)d_out;
    float* mask = nullptr;
    const long long pooled_elems = (long long)BB * LL * HH;
    if ((long long)out_size >= pooled_elems + (long long)BB * LL)
        mask = out + pooled_elems;

    static int smem_set = 0;
    if (!smem_set) {
        cudaFuncSetAttribute(fused_pool,
                             cudaFuncAttributeMaxDynamicSharedMemorySize, DYN_SMEM);
        smem_set = 1;
    }

    fused_pool<<<dim3(LL / BPB, BB), HV, DYN_SMEM>>>(
        (const float4*)hs, ppi, padw, (float4*)out, mask, scale);
}

// round 13
// speedup vs baseline: 1.4692x; 1.4692x over previous
#include <cuda_runtime.h>
#include <math.h>

// Fixed problem shapes
#define BB 8
#define SS 4096
#define HH 1152
#define LL 256
#define HV (HH / 4)    // 288 float4 lanes per row
#define KK 4
#define BPB 4          // buckets per pool block
#define GSZ (HV / BPB) // 72 threads per bucket group

// Scratch (L2-resident)
__device__ int2 g_meta[BB * LL];   // (offset, non-pad count) per bucket
__device__ int  g_tok[BB * SS];    // token lists (non-pad tokens only)

// ---------------------------------------------------------------------------
// Kernel 1: per batch — max_x, kidx, CSR inverted index, mask.
// 1024 threads: halved serial depth vs 512 (prep is latency-bound, 8 blocks).
// ---------------------------------------------------------------------------
__global__ __launch_bounds__(1024) void prep_kernel(
    const int2* __restrict__ ppi,
    const unsigned char* __restrict__ pad,
    float* __restrict__ mask) {
    const int b = blockIdx.x;
    const int t = threadIdx.x;
    const int lane = t & 31;
    const int w = t >> 5;

    __shared__ int smax[32];
    __shared__ int s_factor;
    __shared__ int c_np[LL];
    __shared__ int c_all[LL];
    __shared__ int s_ofs[LL];
    __shared__ int s_cur[LL];
    __shared__ int s_wsum[8];

    const int2* p = ppi + (long long)b * SS;
    const unsigned char* pb = pad + (long long)b * SS;

    int2 v[4];
    unsigned char pd[4];
    #pragma unroll
    for (int i = 0; i < 4; i++) v[i] = p[t + i * 1024];
    #pragma unroll
    for (int i = 0; i < 4; i++) pd[i] = pb[t + i * 1024];

    int mx = 0;
    #pragma unroll
    for (int i = 0; i < 4; i++) mx = max(mx, v[i].x);
    #pragma unroll
    for (int off = 16; off > 0; off >>= 1)
        mx = max(mx, __shfl_xor_sync(0xFFFFFFFFu, mx, off));
    if (lane == 0) smax[w] = mx;
    if (t < LL) { c_np[t] = 0; c_all[t] = 0; s_cur[t] = 0; }
    __syncthreads();
    if (t == 0) {
        int m = smax[0];
        #pragma unroll
        for (int i = 1; i < 32; i++) m = max(m, smax[i]);
        if (m < 0) m = 0;
        s_factor = (m + 1) / KK;
    }
    __syncthreads();
    const int factor = s_factor;

    int ki[4];
    #pragma unroll
    for (int i = 0; i < 4; i++) {
        int x = max(v[i].x, 0);
        int y = max(v[i].y, 0);
        long long kv = (long long)(x / KK) + (long long)factor * (long long)(y / KK);
        ki[i] = (kv >= 0 && kv < LL) ? (int)kv : -1;
        if (ki[i] >= 0) {
            atomicAdd(&c_all[ki[i]], 1);
            if (!pd[i]) atomicAdd(&c_np[ki[i]], 1);
        }
    }
    __syncthreads();

    // exclusive scan over 256 buckets (threads 0..255 = warps 0..7)
    int myc = 0, inc = 0;
    if (t < LL) {
        myc = c_np[t];
        inc = myc;
        #pragma unroll
        for (int d = 1; d < 32; d <<= 1) {
            int up = __shfl_up_sync(0xFFFFFFFFu, inc, d);
            if (lane >= d) inc += up;
        }
        if (lane == 31) s_wsum[w] = inc;
    }
    __syncthreads();
    if (t == 0) {
        int run = 0;
        #pragma unroll
        for (int i = 0; i < 8; i++) { int x = s_wsum[i]; s_wsum[i] = run; run += x; }
    }
    __syncthreads();
    if (t < LL) {
        const int excl = inc - myc + s_wsum[w];
        s_ofs[t] = excl;
        g_meta[b * LL + t] = make_int2(excl, myc);
        if (mask != nullptr)
            mask[(long long)b * LL + t] = (c_all[t] > 0) ? 1.0f : 0.0f;
    }
    __syncthreads();

    #pragma unroll
    for (int i = 0; i < 4; i++) {
        if (ki[i] >= 0 && !pd[i]) {
            const int pos = s_ofs[ki[i]] + atomicAdd(&s_cur[ki[i]], 1);
            g_tok[b * SS + pos] = t + i * 1024;
        }
    }
}

// ---------------------------------------------------------------------------
// Kernel 2: one block per (4 buckets, b) — proven R7 body.
// ---------------------------------------------------------------------------
__global__ __launch_bounds__(HV) void pool_kernel(
    const float4* __restrict__ hs,
    float4* __restrict__ out,
    float scale) {
    const int b = blockIdx.y;
    const int l0 = blockIdx.x * BPB;
    const int bl0 = b * LL + l0;
    const int t = threadIdx.x;

    __shared__ int2 s_meta[BPB];
    __shared__ int s_list[SS];

    if (t < BPB) s_meta[t] = __ldg(&g_meta[bl0 + t]);
    __syncthreads();

    const int start = s_meta[0].x;
    const int total = s_meta[BPB - 1].x + s_meta[BPB - 1].y - start;

    for (int i = t; i < total; i += HV)
        s_list[i] = __ldg(&g_tok[b * SS + start + i]);

    // per-bucket deterministic ordering: group k (72 threads) handles bucket k
    const int k = t / GSZ;
    const int tg = t - k * GSZ;
    const int lo = s_meta[k].x - start;
    const int n = s_meta[k].y;
    int nmax = 0;
    #pragma unroll
    for (int j = 0; j < BPB; j++) nmax = max(nmax, s_meta[j].y);
    __syncthreads();

    if (nmax <= GSZ) {
        int val = 0, r = -1;
        if (tg < n) {
            val = s_list[lo + tg];
            r = 0;
            for (int j = 0; j < n; j++) r += (s_list[lo + j] < val);
        }
        __syncthreads();
        if (r >= 0) s_list[lo + r] = val;
    } else {
        if (tg == 0) {
            for (int i = 1; i < n; i++) {
                const int key = s_list[lo + i];
                int j = i - 1;
                while (j >= 0 && s_list[lo + j] > key) {
                    s_list[lo + j + 1] = s_list[lo + j];
                    j--;
                }
                s_list[lo + j + 1] = key;
            }
        }
    }
    __syncthreads();

    // back-to-back accumulates, no barriers between buckets
    const float4* base4 = hs + (long long)b * SS * HV + t;
    #pragma unroll
    for (int k2 = 0; k2 < BPB; k2++) {
        const int lo2 = s_meta[k2].x - start;
        const int n2 = s_meta[k2].y;
        float4 a0 = make_float4(0.f, 0.f, 0.f, 0.f);
        float4 a1 = a0, a2 = a0, a3 = a0;
        int i = 0;
        for (; i + 4 <= n2; i += 4) {
            const int q0 = s_list[lo2 + i],     q1 = s_list[lo2 + i + 1];
            const int q2 = s_list[lo2 + i + 2], q3 = s_list[lo2 + i + 3];
            const float4 x0 = __ldcs(base4 + (long long)q0 * HV);
            const float4 x1 = __ldcs(base4 + (long long)q1 * HV);
            const float4 x2 = __ldcs(base4 + (long long)q2 * HV);
            const float4 x3 = __ldcs(base4 + (long long)q3 * HV);
            a0.x += x0.x; a0.y += x0.y; a0.z += x0.z; a0.w += x0.w;
            a1.x += x1.x; a1.y += x1.y; a1.z += x1.z; a1.w += x1.w;
            a2.x += x2.x; a2.y += x2.y; a2.z += x2.z; a2.w += x2.w;
            a3.x += x3.x; a3.y += x3.y; a3.z += x3.z; a3.w += x3.w;
        }
        for (; i < n2; i++) {
            const float4 x = __ldcs(base4 + (long long)s_list[lo2 + i] * HV);
            a0.x += x.x; a0.y += x.y; a0.z += x.z; a0.w += x.w;
        }
        float4 r;
        r.x = ((a0.x + a1.x) + (a2.x + a3.x)) * scale;
        r.y = ((a0.y + a1.y) + (a2.y + a3.y)) * scale;
        r.z = ((a0.z + a1.z) + (a2.z + a3.z)) * scale;
        r.w = ((a0.w + a1.w) + (a2.w + a3.w)) * scale;
        __stcs(&out[((long long)(bl0 + k2)) * HV + t], r);
    }
}

// ---------------------------------------------------------------------------
// Launch
// ---------------------------------------------------------------------------
extern "C" void kernel_launch(void* const* d_in, const int* in_sizes, int n_in,
                              void* d_out, int out_size) {
    const float*         hs  = (const float*)d_in[0];
    const int2*          ppi = (const int2*)d_in[1];
    const unsigned char* pad = (const unsigned char*)d_in[2];

    const float scale = sqrtf((float)HH) / (float)(KK * KK);

    float* out  = (float*)d_out;
    float* mask = nullptr;
    const long long pooled_elems = (long long)BB * LL * HH;
    if ((long long)out_size >= pooled_elems + (long long)BB * LL)
        mask = out + pooled_elems;

    prep_kernel<<<BB, 1024>>>(ppi, pad, mask);
    pool_kernel<<<dim3(LL / BPB, BB), HV>>>((const float4*)hs, (float4*)out, scale);
}